// round 6
// baseline (speedup 1.0000x reference)
#include <cuda_runtime.h>
#include <cuda_bf16.h>
#include <math.h>

// B=32, L=1024, C=1024, E=64, TASKS=8, K=2
#define B_ 32
#define L_ 1024
#define C_ 1024
#define E_ 64
#define T_ 8
#define Y_ELEMS (B_ * L_ * C_)       // 33554432
#define GATE_BLOCKS 32
#define SCALE_BLOCKS ((B_ * L_) / 4) // 8192 (4 rows per block)
#define TOTAL_BLOCKS (GATE_BLOCKS + SCALE_BLOCKS)

// Scratch (__device__ globals; allocation-free rule)
__device__ float d_s[B_ * L_];    // combined gate scale per (b,l)
__device__ float d_tm[B_ * L_];   // per-batch token-mask contribution
__device__ float d_pm[B_ * E_];   // masked probs rows
__device__ int   d_flag;          // gate-done counter (0 at entry & exit)
__device__ int   d_done;          // block completion counter (0 at entry & exit)

__device__ __forceinline__ int ld_acquire_gpu(const int* p) {
    int v;
    asm volatile("ld.acquire.gpu.b32 %0, [%1];" : "=r"(v) : "l"(p) : "memory");
    return v;
}
__device__ __forceinline__ void prefetch_l2(const void* p) {
    asm volatile("prefetch.global.L2 [%0];" :: "l"(p));
}

__global__ __launch_bounds__(256, 5) void fused_kernel(
        const float4* __restrict__ x,
        const float*  __restrict__ x2,
        const float*  __restrict__ G,
        const float*  __restrict__ W1,
        const float*  __restrict__ b1,
        const float*  __restrict__ W2,
        float* __restrict__ out) {
    const int tid = threadIdx.x;

    if (blockIdx.x < GATE_BLOCKS) {
        // ============================ GATING ============================
        __shared__ float hg[C_];
        __shared__ float partial[4 * E_];
        __shared__ float probs_sh[E_];
        __shared__ float thresh_sh, sg1_sh, sg2_sh;
        __shared__ int   se1_sh, se2_sh;

        const int b = blockIdx.x;

        // hgate: 4 elems per thread
        {
            float xr[T_];
#pragma unroll
            for (int t = 0; t < T_; t++) xr[t] = x2[b * T_ + t];
#pragma unroll
            for (int j = 0; j < 4; j++) {
                int c = tid + j * 256;
                float h = b1[c];
#pragma unroll
                for (int t = 0; t < T_; t++) h = fmaf(xr[t], W1[t * C_ + c], h);
                h = 0.5f * h * (1.0f + erff(h * 0.70710678118654752f));
                hg[c] = h;
            }
        }
        __syncthreads();

        // logits partials: e = tid&63, chunk ch = tid>>6 covers 256 c's.
        // Two accumulators for ILP; unroll for load MLP.
        {
            const int e  = tid & 63;
            const int c0 = (tid >> 6) * 256;
            float acc0 = 0.0f, acc1 = 0.0f;
#pragma unroll 16
            for (int j = 0; j < 128; j++) {
                int c = c0 + j * 2;
                acc0 = fmaf(hg[c],     __ldg(&W2[c * (2 * E_) + e]),       acc0);
                acc1 = fmaf(hg[c + 1], __ldg(&W2[(c + 1) * (2 * E_) + e]), acc1);
            }
            partial[(tid >> 6) * E_ + e] = acc0 + acc1;
        }
        __syncthreads();

        if (tid < E_) {
            probs_sh[tid] = partial[tid] + partial[E_ + tid]
                          + partial[2 * E_ + tid] + partial[3 * E_ + tid];
        }
        __syncthreads();

        // warp 0: softmax + top-2 via shuffles
        if (tid < 32) {
            const float la = probs_sh[tid];
            const float lb = probs_sh[tid + 32];

            float m = fmaxf(la, lb);
#pragma unroll
            for (int off = 16; off > 0; off >>= 1)
                m = fmaxf(m, __shfl_xor_sync(0xffffffffu, m, off));

            float ea = expf(la - m);
            float eb = expf(lb - m);
            float s = ea + eb;
#pragma unroll
            for (int off = 16; off > 0; off >>= 1)
                s += __shfl_xor_sync(0xffffffffu, s, off);
            const float inv = 1.0f / s;

            float pa = fmaf(ea, inv, 0.0001f);
            float pb = fmaf(eb, inv, 0.0001f);
            probs_sh[tid]      = pa;
            probs_sh[tid + 32] = pb;

            float t1, t2; int i1, i2;
            if (pa >= pb) { t1 = pa; i1 = tid;      t2 = pb; i2 = tid + 32; }
            else          { t1 = pb; i1 = tid + 32; t2 = pa; i2 = tid; }
#pragma unroll
            for (int off = 16; off > 0; off >>= 1) {
                float o1 = __shfl_xor_sync(0xffffffffu, t1, off);
                int  oi1 = __shfl_xor_sync(0xffffffffu, i1, off);
                float o2 = __shfl_xor_sync(0xffffffffu, t2, off);
                int  oi2 = __shfl_xor_sync(0xffffffffu, i2, off);
                if (o1 > t1) {
                    if (t1 > o2) { t2 = t1; i2 = i1; }
                    else         { t2 = o2; i2 = oi2; }
                    t1 = o1; i1 = oi1;
                } else if (o1 > t2) {
                    t2 = o1; i2 = oi1;
                }
            }
            if (tid == 0) {
                se1_sh = i1; se2_sh = i2;
                sg1_sh = t1; sg2_sh = t2;
                thresh_sh = t2;
            }
        }
        __syncthreads();

        if (tid < E_) {
            float p = probs_sh[tid];
            d_pm[b * E_ + tid] = (p >= thresh_sh) ? p : 0.0f;
        }

        // per-(b,l) scale + token-mask contribution; 4 l's per thread
#pragma unroll
        for (int j = 0; j < 4; j++) {
            int l = tid + j * 256;
            float ga = G[((size_t)(b * E_ + se1_sh)) * L_ + l];
            float gb = G[((size_t)(b * E_ + se2_sh)) * L_ + l];
            d_s[b * L_ + l]  = fmaf(sg1_sh, ga, sg2_sh * gb);
            d_tm[b * L_ + l] = ga + gb;
        }

        __threadfence();
        __syncthreads();
        if (tid == 0) atomicAdd(&d_flag, 1);
    } else {
        // ============================ SCALE =============================
        const int row0 = (blockIdx.x - GATE_BLOCKS) * 4;
        const int t = tid;

        const size_t i0 = (size_t)(row0 + 0) * 256 + t;
        const size_t i1 = (size_t)(row0 + 1) * 256 + t;
        const size_t i2 = (size_t)(row0 + 2) * 256 + t;
        const size_t i3 = (size_t)(row0 + 3) * 256 + t;

        // Issue streaming loads (in flight during any wait).
        float4 v0 = __ldcs(&x[i0]);
        float4 v1 = __ldcs(&x[i1]);
        float4 v2 = __ldcs(&x[i2]);
        float4 v3 = __ldcs(&x[i3]);

        // Keep DRAM busy during the gate window: prefetch next-wave region
        // into L2 (no register cost). ~1024 blocks ahead = 4096 rows.
        {
            const size_t pf = (size_t)4096 * 256;  // 4096 rows in float4 units
            if (row0 + 4096 < B_ * L_) {
                prefetch_l2(&x[i0 + pf]);
                prefetch_l2(&x[i1 + pf]);
                prefetch_l2(&x[i2 + pf]);
                prefetch_l2(&x[i3 + pf]);
            }
        }

        // Wait for gate data readiness.
        if (t == 0) {
            while (ld_acquire_gpu(&d_flag) < GATE_BLOCKS) __nanosleep(64);
        }
        __syncthreads();

        const float s0 = d_s[row0 + 0];
        const float s1 = d_s[row0 + 1];
        const float s2 = d_s[row0 + 2];
        const float s3 = d_s[row0 + 3];

        v0.x *= s0; v0.y *= s0; v0.z *= s0; v0.w *= s0;
        v1.x *= s1; v1.y *= s1; v1.z *= s1; v1.w *= s1;
        v2.x *= s2; v2.y *= s2; v2.z *= s2; v2.w *= s2;
        v3.x *= s3; v3.y *= s3; v3.z *= s3; v3.w *= s3;

        float4* y = (float4*)out;
        __stcs(&y[i0], v0);
        __stcs(&y[i1], v1);
        __stcs(&y[i2], v2);
        __stcs(&y[i3], v3);

        // Block 32: masks. Layout: [y (32M), expert_mask (64), token_mask (1024)]
        if (blockIdx.x == GATE_BLOCKS) {
#pragma unroll
            for (int j = 0; j < 4; j++) {
                int l = t + j * 256;
                float tm = 0.0f;
#pragma unroll
                for (int b = 0; b < B_; b++) tm += d_tm[b * L_ + l];
                out[Y_ELEMS + E_ + l] = tm;
            }
            if (t < E_) {
                float em = 0.0f;
#pragma unroll
                for (int b = 0; b < B_; b++) em += d_pm[b * E_ + t];
                out[Y_ELEMS + t] = em;
            }
        }
    }

    // Reset handshake for the next graph replay (deterministic).
    __syncthreads();
    if (tid == 0) {
        int old = atomicAdd(&d_done, 1);
        if (old == TOTAL_BLOCKS - 1) {
            d_flag = 0;
            d_done = 0;
        }
    }
}

extern "C" void kernel_launch(void* const* d_in, const int* in_sizes, int n_in,
                              void* d_out, int out_size) {
    const float* x  = (const float*)d_in[0];  // input_features (32,1024,1024)
    const float* x2 = (const float*)d_in[1];  // input_features2 (32,8)
    const float* G  = (const float*)d_in[2];  // G (32,64,1024)
    const float* W1 = (const float*)d_in[3];  // W1 (8,1024)
    const float* b1 = (const float*)d_in[4];  // b1 (1024,)
    const float* W2 = (const float*)d_in[5];  // W2 (1024,128)
    float* out = (float*)d_out;

    fused_kernel<<<TOTAL_BLOCKS, 256>>>((const float4*)x, x2, G, W1, b1, W2, out);
}

// round 7
// speedup vs baseline: 1.9264x; 1.9264x over previous
#include <cuda_runtime.h>
#include <cuda_bf16.h>
#include <math.h>

// B=32, L=1024, C=1024, E=64, TASKS=8, K=2
#define B_ 32
#define L_ 1024
#define C_ 1024
#define E_ 64
#define T_ 8
#define Y_ELEMS (B_ * L_ * C_)         // 33554432
#define SCALE_BLOCKS ((B_ * L_) / 4)   // 8192

// Scratch (__device__ globals; allocation-free rule)
__device__ float d_s[B_ * L_];    // combined gate scale per (b,l)
__device__ float d_tm[B_ * L_];   // per-batch token-mask contribution
__device__ float d_pm[B_ * E_];   // masked probs rows

// ---------------------------------------------------------------------------
// Kernel 1: gating. One block of 1024 threads per batch.
// Logits via float4 W2 loads: 4 FMAs per ~8 instructions (issue-bound fix).
// ---------------------------------------------------------------------------
__global__ __launch_bounds__(1024) void gate_kernel(
        const float* __restrict__ x2,
        const float* __restrict__ W1,
        const float* __restrict__ b1,
        const float* __restrict__ W2,
        const float* __restrict__ G) {
    __shared__ float hg[C_];
    __shared__ float partial[64 * 65];   // [chunk][expert], padded stride 65
    __shared__ float probs_sh[E_];
    __shared__ float thresh_sh, sg1_sh, sg2_sh;
    __shared__ int   se1_sh, se2_sh;

    const int b = blockIdx.x;
    const int tid = threadIdx.x;

    // Let the dependent scale kernel launch early (PDL).
    cudaTriggerProgrammaticLaunchCompletion();

    // --- hgate: one element per thread ---
    {
        float xr[T_];
#pragma unroll
        for (int t = 0; t < T_; t++) xr[t] = x2[b * T_ + t];
        float h = b1[tid];
#pragma unroll
        for (int t = 0; t < T_; t++) h = fmaf(xr[t], W1[t * C_ + tid], h);
        h = 0.5f * h * (1.0f + erff(h * 0.70710678118654752f));
        hg[tid] = h;
    }
    __syncthreads();

    // --- logits partials: thread = (chunk ch = tid>>4, expert-group eg = tid&15)
    //     chunk covers 16 c's; each iteration does 4 experts via one float4 load.
    {
        const int ch = tid >> 4;          // 0..63
        const int eg = tid & 15;          // 0..15 -> experts 4eg..4eg+3
        const int c0 = ch * 16;
        const float4* W2v = (const float4*)W2;  // row stride 32 float4 (128 floats)
        float4 acc = make_float4(0.f, 0.f, 0.f, 0.f);
#pragma unroll
        for (int j = 0; j < 16; j++) {
            const int c = c0 + j;
            const float h = hg[c];
            const float4 w = __ldg(&W2v[c * 32 + eg]);
            acc.x = fmaf(h, w.x, acc.x);
            acc.y = fmaf(h, w.y, acc.y);
            acc.z = fmaf(h, w.z, acc.z);
            acc.w = fmaf(h, w.w, acc.w);
        }
        float* p = &partial[ch * 65 + eg * 4];
        p[0] = acc.x; p[1] = acc.y; p[2] = acc.z; p[3] = acc.w;
    }
    __syncthreads();

    // --- reduce 64 chunks per expert ---
    if (tid < E_) {
        float acc = 0.0f;
#pragma unroll
        for (int ch = 0; ch < 64; ch++) acc += partial[ch * 65 + tid];
        probs_sh[tid] = acc;   // logits
    }
    __syncthreads();

    // --- warp 0: softmax + top-2 via shuffles ---
    if (tid < 32) {
        const float la = probs_sh[tid];
        const float lb = probs_sh[tid + 32];

        float m = fmaxf(la, lb);
#pragma unroll
        for (int off = 16; off > 0; off >>= 1)
            m = fmaxf(m, __shfl_xor_sync(0xffffffffu, m, off));

        float ea = expf(la - m);
        float eb = expf(lb - m);
        float s = ea + eb;
#pragma unroll
        for (int off = 16; off > 0; off >>= 1)
            s += __shfl_xor_sync(0xffffffffu, s, off);
        const float inv = 1.0f / s;

        float pa = fmaf(ea, inv, 0.0001f);
        float pb = fmaf(eb, inv, 0.0001f);
        probs_sh[tid]      = pa;
        probs_sh[tid + 32] = pb;

        float t1, t2; int i1, i2;
        if (pa >= pb) { t1 = pa; i1 = tid;      t2 = pb; i2 = tid + 32; }
        else          { t1 = pb; i1 = tid + 32; t2 = pa; i2 = tid; }
#pragma unroll
        for (int off = 16; off > 0; off >>= 1) {
            float o1 = __shfl_xor_sync(0xffffffffu, t1, off);
            int  oi1 = __shfl_xor_sync(0xffffffffu, i1, off);
            float o2 = __shfl_xor_sync(0xffffffffu, t2, off);
            int  oi2 = __shfl_xor_sync(0xffffffffu, i2, off);
            if (o1 > t1) {
                if (t1 > o2) { t2 = t1; i2 = i1; }
                else         { t2 = o2; i2 = oi2; }
                t1 = o1; i1 = oi1;
            } else if (o1 > t2) {
                t2 = o1; i2 = oi1;
            }
        }
        if (tid == 0) {
            se1_sh = i1; se2_sh = i2;
            sg1_sh = t1; sg2_sh = t2;
            thresh_sh = t2;
        }
    }
    __syncthreads();

    // --- masked probs row for expert_mask ---
    if (tid < E_) {
        float p = probs_sh[tid];
        d_pm[b * E_ + tid] = (p >= thresh_sh) ? p : 0.0f;
    }

    // --- per-(b,l) scale + token-mask contribution (coalesced G reads) ---
    {
        float ga = G[((size_t)(b * E_ + se1_sh)) * L_ + tid];
        float gb = G[((size_t)(b * E_ + se2_sh)) * L_ + tid];
        d_s[b * L_ + tid]  = fmaf(sg1_sh, ga, sg2_sh * gb);
        d_tm[b * L_ + tid] = ga + gb;
    }
}

// ---------------------------------------------------------------------------
// Kernel 2: y = x * s  (bandwidth-bound, at roofline). 4 rows per block.
// PDL secondary: prelude loads, then grid-dependency wait, then mul+store.
// Block 0 also produces the two masks.
// ---------------------------------------------------------------------------
__global__ __launch_bounds__(256) void scale_kernel(
        const float4* __restrict__ x,
        float4* __restrict__ y,
        float* __restrict__ out) {
    const int row0 = blockIdx.x * 4;
    const int t = threadIdx.x;

    const size_t i0 = (size_t)(row0 + 0) * 256 + t;
    const size_t i1 = (size_t)(row0 + 1) * 256 + t;
    const size_t i2 = (size_t)(row0 + 2) * 256 + t;
    const size_t i3 = (size_t)(row0 + 3) * 256 + t;

    // Prelude: streaming loads in flight before the dependency point.
    float4 v0 = __ldcs(&x[i0]);
    float4 v1 = __ldcs(&x[i1]);
    float4 v2 = __ldcs(&x[i2]);
    float4 v3 = __ldcs(&x[i3]);

    cudaGridDependencySynchronize();

    const float s0 = d_s[row0 + 0];
    const float s1 = d_s[row0 + 1];
    const float s2 = d_s[row0 + 2];
    const float s3 = d_s[row0 + 3];

    v0.x *= s0; v0.y *= s0; v0.z *= s0; v0.w *= s0;
    v1.x *= s1; v1.y *= s1; v1.z *= s1; v1.w *= s1;
    v2.x *= s2; v2.y *= s2; v2.z *= s2; v2.w *= s2;
    v3.x *= s3; v3.y *= s3; v3.z *= s3; v3.w *= s3;

    __stcs(&y[i0], v0);
    __stcs(&y[i1], v1);
    __stcs(&y[i2], v2);
    __stcs(&y[i3], v3);

    // Block 0: masks. Layout: [y (32M), expert_mask (64), token_mask (1024)]
    if (blockIdx.x == 0) {
#pragma unroll
        for (int j = 0; j < 4; j++) {
            int l = t + j * 256;
            float tm = 0.0f;
#pragma unroll
            for (int b = 0; b < B_; b++) tm += d_tm[b * L_ + l];
            out[Y_ELEMS + E_ + l] = tm;
        }
        if (t < E_) {
            float em = 0.0f;
#pragma unroll
            for (int b = 0; b < B_; b++) em += d_pm[b * E_ + t];
            out[Y_ELEMS + t] = em;
        }
    }
}

// ---------------------------------------------------------------------------
extern "C" void kernel_launch(void* const* d_in, const int* in_sizes, int n_in,
                              void* d_out, int out_size) {
    const float* x  = (const float*)d_in[0];  // input_features (32,1024,1024)
    const float* x2 = (const float*)d_in[1];  // input_features2 (32,8)
    const float* G  = (const float*)d_in[2];  // G (32,64,1024)
    const float* W1 = (const float*)d_in[3];  // W1 (8,1024)
    const float* b1 = (const float*)d_in[4];  // b1 (1024,)
    const float* W2 = (const float*)d_in[5];  // W2 (1024,128)
    float* out = (float*)d_out;

    gate_kernel<<<B_, 1024>>>(x2, W1, b1, W2, G);

    // PDL launch of the scale kernel.
    cudaLaunchConfig_t cfg = {};
    cfg.gridDim  = dim3(SCALE_BLOCKS, 1, 1);
    cfg.blockDim = dim3(256, 1, 1);
    cfg.dynamicSmemBytes = 0;
    cfg.stream = 0;
    cudaLaunchAttribute attrs[1];
    attrs[0].id = cudaLaunchAttributeProgrammaticStreamSerialization;
    attrs[0].val.programmaticStreamSerializationAllowed = 1;
    cfg.attrs = attrs;
    cfg.numAttrs = 1;
    cudaLaunchKernelEx(&cfg, scale_kernel, (const float4*)x, (float4*)out, out);
}